// round 16
// baseline (speedup 1.0000x reference)
#include <cuda_runtime.h>
#include <cuda_bf16.h>

#define DIM    2048
#define BATCH  32
#define KTOP   256
#define LOG2E  1.44269504f

// sorted chunk keys (monotonic u32, value-only) [b][chunk(256-wide)][256]
__device__ __align__(16) unsigned int g_key[BATCH * DIM];
// inclusive prefix sums of values in chunk-sorted order, same layout
__device__ __align__(16) float g_pref[BATCH * DIM];
// Bsum * log2e, original index order
__device__ __align__(16) float g_bsum[BATCH * DIM];
// top-256 by global rank: slot r-1792 holds (s*log2e, B*log2e) of rank-r element
__device__ __align__(16) float g_topv[BATCH * KTOP];
__device__ __align__(16) float g_topB[BATCH * KTOP];

__device__ __forceinline__ float ex2f(float x) {
    float r; asm("ex2.approx.ftz.f32 %0, %1;" : "=f"(r) : "f"(x)); return r;
}
__device__ __forceinline__ float rcpf(float x) {
    float r; asm("rcp.approx.f32 %0, %1;" : "=f"(r) : "f"(x)); return r;
}
__device__ __forceinline__ unsigned int monokey(float f) {
    unsigned int u = __float_as_uint(f);
    return u ^ (((unsigned int)((int)u >> 31)) | 0x80000000u);
}
__device__ __forceinline__ float unmono(unsigned int u) {
    return __uint_as_float(u ^ ((~((unsigned int)((int)u >> 31))) | 0x80000000u));
}

// ---------------------------------------------------------------------------
// Kernel A: rank-count sort of 256-element chunks, TWO independent chunks per
// 512-thread block. Grid (4 chunk-pairs, 32 b) = 128 blocks = one full wave.
// Tie-safe scatter via smem atomic slot handout; per-chunk inclusive prefix
// sums.
// ---------------------------------------------------------------------------
__global__ __launch_bounds__(512) void chunk_rank_kernel(const float* __restrict__ scores) {
    __shared__ __align__(16) unsigned int sk[512];
    __shared__ unsigned int ssort[512];
    __shared__ int ctr[512];
    __shared__ float wtot[2][8];
    const int cp = blockIdx.x, b = blockIdx.y, t = threadIdx.x;
    const int sub = t >> 8;                 // which of the two chunks
    const int lane = t & 31, w = t >> 5;
    const int ws = w & 7;                   // warp-in-subchunk
    const int gi = (cp << 9) + t;

    const unsigned int K = monokey(scores[(b << 11) + gi]);
    sk[t] = K;
    ctr[t] = 0;
    __syncthreads();

    // strict-less count within own 256-chunk: 64 LDS.128 + 256 ISETP/IADD
    int r0 = 0, r1 = 0, r2 = 0, r3 = 0;
    const uint4* s4 = (const uint4*)(sk + (sub << 8));
    #pragma unroll 16
    for (int j = 0; j < 64; j++) {
        uint4 v = s4[j];
        r0 += (v.x < K);
        r1 += (v.y < K);
        r2 += (v.z < K);
        r3 += (v.w < K);
    }
    const int r = (r0 + r1) + (r2 + r3);

    // tie-safe scatter within own chunk
    const int off = atomicAdd(&ctr[(sub << 8) + r], 1);
    ssort[(sub << 8) + r + off] = K;
    __syncthreads();

    const unsigned int Ks = ssort[t];
    const float v = unmono(Ks);

    // inclusive scan per 256-subchunk (8 warps each)
    float x = v;
    #pragma unroll
    for (int o = 1; o < 32; o <<= 1) {
        float y = __shfl_up_sync(0xffffffffu, x, o);
        if (lane >= o) x += y;
    }
    if (lane == 31) wtot[sub][ws] = x;
    __syncthreads();
    float offs = 0.f;
    #pragma unroll
    for (int ww = 0; ww < 7; ww++) if (ww < ws) offs += wtot[sub][ww];

    g_key[(b << 11) + gi]  = Ks;
    g_pref[(b << 11) + gi] = offs + x;
}

// ---------------------------------------------------------------------------
// Kernel B: per-element rank + smaller-sum via 8 interleaved branchless
// lower-bound searches over the 8 sorted 256-chunks staged in smem.
// Grid (4, 32) = 128 blocks x 512 threads — one wave.
// B_i = s_i*(2r-n) + T - 2P. Upper-bound (tie-extent) search only near the
// top boundary; rank range [r, ru) fills the top-256 slots.
// ---------------------------------------------------------------------------
__global__ __launch_bounds__(512) void bsum_search_kernel(const float* __restrict__ scores) {
    __shared__ __align__(16) unsigned int skey[DIM];   // 8 KB
    __shared__ __align__(16) float spref[DIM];         // 8 KB
    const int ic = blockIdx.x, b = blockIdx.y, t = threadIdx.x;

    {   // stage the whole row (512 threads x 1 uint4/float4)
        ((uint4*)skey)[t]   = ((const uint4*)(g_key  + (b << 11)))[t];
        ((float4*)spref)[t] = ((const float4*)(g_pref + (b << 11)))[t];
    }
    __syncthreads();

    const int i = (ic << 9) + t;
    const float s = scores[(b << 11) + i];
    const unsigned int K = monokey(s);

    // 8 interleaved branchless lower-bound searches over 256-entry chunks
    int pl[8];
    #pragma unroll
    for (int c = 0; c < 8; c++) pl[c] = 0;
    #pragma unroll
    for (int st = 128; st >= 1; st >>= 1) {
        #pragma unroll
        for (int c = 0; c < 8; c++)
            if (skey[(c << 8) + pl[c] + st - 1] < K) pl[c] += st;
    }
    #pragma unroll
    for (int c = 0; c < 8; c++)
        if (skey[(c << 8) + pl[c]] < K) pl[c]++;     // pl in [0,256]

    int r = 0;
    float P = 0.f, T = 0.f;
    #pragma unroll
    for (int c = 0; c < 8; c++) {
        r += pl[c];
        if (pl[c] > 0) P += spref[(c << 8) + pl[c] - 1];
        T += spref[(c << 8) + 255];
    }

    const float B = fmaf(s, (float)(2 * r - DIM), T - 2.f * P);
    g_bsum[(b << 11) + i] = B * LOG2E;

    // top-256 fill: only elements near the boundary need the tie extent
    if (r >= DIM - KTOP - 16) {
        const unsigned int Ku = K + 1;               // upper = lower_bound(K+1)
        int pu[8];
        #pragma unroll
        for (int c = 0; c < 8; c++) pu[c] = 0;
        #pragma unroll
        for (int st = 128; st >= 1; st >>= 1) {
            #pragma unroll
            for (int c = 0; c < 8; c++)
                if (skey[(c << 8) + pu[c] + st - 1] < Ku) pu[c] += st;
        }
        int ru = 0;
        #pragma unroll
        for (int c = 0; c < 8; c++) {
            if (skey[(c << 8) + pu[c]] < Ku) pu[c]++;
            ru += pu[c];
        }
        if (ru > DIM - KTOP) {
            int lo = r > (DIM - KTOP) ? r : (DIM - KTOP);
            for (int rr = lo; rr < ru; rr++) {       // almost always 1 iter
                g_topv[(b << 8) + rr - (DIM - KTOP)] = s * LOG2E;
                g_topB[(b << 8) + rr - (DIM - KTOP)] = B * LOG2E;
            }
        }
    }
}

// ---------------------------------------------------------------------------
// Kernel C: fused softmax writer, SINGLE-k loop, register-lean for 7
// blocks/SM (one full wave at grid 1024). M is analytic (rank 2047-k element
// => slot 255-k): 1 barrier/k, double-buffered reduction slots.
// Grid (32 kg, 32 b) x 256 threads.
// ---------------------------------------------------------------------------
__global__ __launch_bounds__(256, 7) void softmax_kernel(const float* __restrict__ scores,
                                                         float* __restrict__ out) {
    __shared__ float redS[16];                 // 2 buffers x 8 warp sums
    const int kg = blockIdx.x, b = blockIdx.y, t = threadIdx.x;
    const int lane = t & 31, w = t >> 5;

    const float4* sc4 = (const float4*)(scores + (b << 11));
    const float4* bs4 = (const float4*)(g_bsum + (b << 11));
    float4 a0 = sc4[t], a1 = sc4[t + 256];
    const float4 c0 = bs4[t], c1 = bs4[t + 256];
    a0.x *= LOG2E; a0.y *= LOG2E; a0.z *= LOG2E; a0.w *= LOG2E;
    a1.x *= LOG2E; a1.y *= LOG2E; a1.z *= LOG2E; a1.w *= LOG2E;

    #pragma unroll
    for (int kk = 0; kk < 8; kk++) {
        const int k = (kg << 3) + kk;
        const float scal = (float)(DIM - 1 - 2 * k);
        const float M = fmaf(scal, __ldg(&g_topv[(b << 8) + 255 - k]),
                             -__ldg(&g_topB[(b << 8) + 255 - k]));

        float e[8];
        e[0] = ex2f(fmaf(a0.x, scal, -c0.x) - M);
        e[1] = ex2f(fmaf(a0.y, scal, -c0.y) - M);
        e[2] = ex2f(fmaf(a0.z, scal, -c0.z) - M);
        e[3] = ex2f(fmaf(a0.w, scal, -c0.w) - M);
        e[4] = ex2f(fmaf(a1.x, scal, -c1.x) - M);
        e[5] = ex2f(fmaf(a1.y, scal, -c1.y) - M);
        e[6] = ex2f(fmaf(a1.z, scal, -c1.z) - M);
        e[7] = ex2f(fmaf(a1.w, scal, -c1.w) - M);

        float s = ((e[0] + e[1]) + (e[2] + e[3])) + ((e[4] + e[5]) + (e[6] + e[7]));
        #pragma unroll
        for (int o = 16; o; o >>= 1) s += __shfl_xor_sync(0xffffffffu, s, o);
        const int p = (kk & 1) << 3;
        if (lane == 0) redS[p + w] = s;
        __syncthreads();                     // one barrier per k
        float S = redS[p + (lane & 7)];
        #pragma unroll
        for (int o = 4; o; o >>= 1) S += __shfl_xor_sync(0xffffffffu, S, o);

        const float inv = rcpf(S);
        float4* o4 = (float4*)(out + ((size_t)((b << 8) + k) << 11));
        o4[t]       = make_float4(e[0] * inv, e[1] * inv, e[2] * inv, e[3] * inv);
        o4[t + 256] = make_float4(e[4] * inv, e[5] * inv, e[6] * inv, e[7] * inv);
    }
}

extern "C" void kernel_launch(void* const* d_in, const int* in_sizes, int n_in,
                              void* d_out, int out_size) {
    const float* scores = (const float*)d_in[0];
    float* out = (float*)d_out;

    chunk_rank_kernel<<<dim3(4, BATCH), 512>>>(scores);
    bsum_search_kernel<<<dim3(4, BATCH), 512>>>(scores);
    softmax_kernel<<<dim3(KTOP / 8, BATCH), 256>>>(scores, out);
}

// round 17
// speedup vs baseline: 1.0770x; 1.0770x over previous
#include <cuda_runtime.h>
#include <cuda_bf16.h>

#define DIM    2048
#define BATCH  32
#define KTOP   256
#define LOG2E  1.44269504f

// sorted chunk keys (monotonic u32, value-only) [b][chunk(256-wide)][256]
__device__ __align__(16) unsigned int g_key[BATCH * DIM];
// inclusive prefix sums of values in chunk-sorted order, same layout
__device__ __align__(16) float g_pref[BATCH * DIM];
// Bsum * log2e, original index order
__device__ __align__(16) float g_bsum[BATCH * DIM];
// top-256 by global rank: slot r-1792 holds (s*log2e, B*log2e) of rank-r element
__device__ __align__(16) float g_topv[BATCH * KTOP];
__device__ __align__(16) float g_topB[BATCH * KTOP];

__device__ __forceinline__ float ex2f(float x) {
    float r; asm("ex2.approx.ftz.f32 %0, %1;" : "=f"(r) : "f"(x)); return r;
}
__device__ __forceinline__ float rcpf(float x) {
    float r; asm("rcp.approx.f32 %0, %1;" : "=f"(r) : "f"(x)); return r;
}
__device__ __forceinline__ unsigned int monokey(float f) {
    unsigned int u = __float_as_uint(f);
    return u ^ (((unsigned int)((int)u >> 31)) | 0x80000000u);
}
__device__ __forceinline__ float unmono(unsigned int u) {
    return __uint_as_float(u ^ ((~((unsigned int)((int)u >> 31))) | 0x80000000u));
}

// ---- packed f32x2 helpers (Blackwell) ----
__device__ __forceinline__ unsigned long long pack2(float lo, float hi) {
    unsigned long long r;
    asm("mov.b64 %0, {%1, %2};" : "=l"(r) : "f"(lo), "f"(hi));
    return r;
}
__device__ __forceinline__ void unpack2(unsigned long long v, float& lo, float& hi) {
    asm("mov.b64 {%0, %1}, %2;" : "=f"(lo), "=f"(hi) : "l"(v));
}
__device__ __forceinline__ unsigned long long fma2(unsigned long long a,
                                                   unsigned long long b,
                                                   unsigned long long c) {
    unsigned long long r;
    asm("fma.rn.f32x2 %0, %1, %2, %3;" : "=l"(r) : "l"(a), "l"(b), "l"(c));
    return r;
}
__device__ __forceinline__ unsigned long long add2(unsigned long long a,
                                                   unsigned long long b) {
    unsigned long long r;
    asm("add.rn.f32x2 %0, %1, %2;" : "=l"(r) : "l"(a), "l"(b));
    return r;
}

// ---------------------------------------------------------------------------
// Kernel A: rank-count sort of 256-element chunks, TWO independent chunks per
// 512-thread block. Grid (4 chunk-pairs, 32 b) = 128 blocks = one full wave.
// Tie-safe scatter via smem atomic slot handout; per-chunk inclusive prefix
// sums.
// ---------------------------------------------------------------------------
__global__ __launch_bounds__(512) void chunk_rank_kernel(const float* __restrict__ scores) {
    __shared__ __align__(16) unsigned int sk[512];
    __shared__ unsigned int ssort[512];
    __shared__ int ctr[512];
    __shared__ float wtot[2][8];
    const int cp = blockIdx.x, b = blockIdx.y, t = threadIdx.x;
    const int sub = t >> 8;                 // which of the two chunks
    const int lane = t & 31, w = t >> 5;
    const int ws = w & 7;                   // warp-in-subchunk
    const int gi = (cp << 9) + t;

    const unsigned int K = monokey(scores[(b << 11) + gi]);
    sk[t] = K;
    ctr[t] = 0;
    __syncthreads();

    // strict-less count within own 256-chunk: 64 LDS.128 + 256 ISETP/IADD
    int r0 = 0, r1 = 0, r2 = 0, r3 = 0;
    const uint4* s4 = (const uint4*)(sk + (sub << 8));
    #pragma unroll 16
    for (int j = 0; j < 64; j++) {
        uint4 v = s4[j];
        r0 += (v.x < K);
        r1 += (v.y < K);
        r2 += (v.z < K);
        r3 += (v.w < K);
    }
    const int r = (r0 + r1) + (r2 + r3);

    // tie-safe scatter within own chunk
    const int off = atomicAdd(&ctr[(sub << 8) + r], 1);
    ssort[(sub << 8) + r + off] = K;
    __syncthreads();

    const unsigned int Ks = ssort[t];
    const float v = unmono(Ks);

    // inclusive scan per 256-subchunk (8 warps each)
    float x = v;
    #pragma unroll
    for (int o = 1; o < 32; o <<= 1) {
        float y = __shfl_up_sync(0xffffffffu, x, o);
        if (lane >= o) x += y;
    }
    if (lane == 31) wtot[sub][ws] = x;
    __syncthreads();
    float offs = 0.f;
    #pragma unroll
    for (int ww = 0; ww < 7; ww++) if (ww < ws) offs += wtot[sub][ww];

    g_key[(b << 11) + gi]  = Ks;
    g_pref[(b << 11) + gi] = offs + x;
}

// ---------------------------------------------------------------------------
// Kernel B: per-element rank + smaller-sum via 8 interleaved branchless
// lower-bound searches over the 8 sorted 256-chunks staged in smem.
// Grid (4, 32) = 128 blocks x 512 threads — one wave.
// B_i = s_i*(2r-n) + T - 2P. Upper-bound (tie-extent) search only near the
// top boundary; rank range [r, ru) fills the top-256 slots.
// ---------------------------------------------------------------------------
__global__ __launch_bounds__(512) void bsum_search_kernel(const float* __restrict__ scores) {
    __shared__ __align__(16) unsigned int skey[DIM];   // 8 KB
    __shared__ __align__(16) float spref[DIM];         // 8 KB
    const int ic = blockIdx.x, b = blockIdx.y, t = threadIdx.x;

    {   // stage the whole row (512 threads x 1 uint4/float4)
        ((uint4*)skey)[t]   = ((const uint4*)(g_key  + (b << 11)))[t];
        ((float4*)spref)[t] = ((const float4*)(g_pref + (b << 11)))[t];
    }
    __syncthreads();

    const int i = (ic << 9) + t;
    const float s = scores[(b << 11) + i];
    const unsigned int K = monokey(s);

    // 8 interleaved branchless lower-bound searches over 256-entry chunks
    int pl[8];
    #pragma unroll
    for (int c = 0; c < 8; c++) pl[c] = 0;
    #pragma unroll
    for (int st = 128; st >= 1; st >>= 1) {
        #pragma unroll
        for (int c = 0; c < 8; c++)
            if (skey[(c << 8) + pl[c] + st - 1] < K) pl[c] += st;
    }
    #pragma unroll
    for (int c = 0; c < 8; c++)
        if (skey[(c << 8) + pl[c]] < K) pl[c]++;     // pl in [0,256]

    int r = 0;
    float P = 0.f, T = 0.f;
    #pragma unroll
    for (int c = 0; c < 8; c++) {
        r += pl[c];
        if (pl[c] > 0) P += spref[(c << 8) + pl[c] - 1];
        T += spref[(c << 8) + 255];
    }

    const float B = fmaf(s, (float)(2 * r - DIM), T - 2.f * P);
    g_bsum[(b << 11) + i] = B * LOG2E;

    // top-256 fill: only elements near the boundary need the tie extent
    if (r >= DIM - KTOP - 16) {
        const unsigned int Ku = K + 1;               // upper = lower_bound(K+1)
        int pu[8];
        #pragma unroll
        for (int c = 0; c < 8; c++) pu[c] = 0;
        #pragma unroll
        for (int st = 128; st >= 1; st >>= 1) {
            #pragma unroll
            for (int c = 0; c < 8; c++)
                if (skey[(c << 8) + pu[c] + st - 1] < Ku) pu[c] += st;
        }
        int ru = 0;
        #pragma unroll
        for (int c = 0; c < 8; c++) {
            if (skey[(c << 8) + pu[c]] < Ku) pu[c]++;
            ru += pu[c];
        }
        if (ru > DIM - KTOP) {
            int lo = r > (DIM - KTOP) ? r : (DIM - KTOP);
            for (int rr = lo; rr < ru; rr++) {       // almost always 1 iter
                g_topv[(b << 8) + rr - (DIM - KTOP)] = s * LOG2E;
                g_topB[(b << 8) + rr - (DIM - KTOP)] = B * LOG2E;
            }
        }
    }
}

// ---------------------------------------------------------------------------
// Kernel C: fused softmax writer, PAIRED k's (proven R12 structure) with the
// logit pipeline in PACKED f32x2 (FFMA2/ADD2 — half the fma-pipe slots;
// packed result halves feed ex2 directly from the register pair).
// M analytic (slot 255-k). One barrier per 2 k's, double-buffered slots.
// Grid (32 kg, 32 b) x 256 threads. Natural register allocation (no forced
// occupancy — R13 lesson).
// ---------------------------------------------------------------------------
__global__ __launch_bounds__(256) void softmax_kernel(const float* __restrict__ scores,
                                                      float* __restrict__ out) {
    __shared__ float redS[32];                 // 2 buffers x (8+8) warp sums
    const int kg = blockIdx.x, b = blockIdx.y, t = threadIdx.x;
    const int lane = t & 31, w = t >> 5;

    const float4* sc4 = (const float4*)(scores + (b << 11));
    const float4* bs4 = (const float4*)(g_bsum + (b << 11));
    float4 a0 = sc4[t], a1 = sc4[t + 256];
    const float4 c0 = bs4[t], c1 = bs4[t + 256];

    // pack once: A = a*log2e pairs, NC = -c pairs
    unsigned long long A[4], NC[4];
    A[0] = pack2(a0.x * LOG2E, a0.y * LOG2E);
    A[1] = pack2(a0.z * LOG2E, a0.w * LOG2E);
    A[2] = pack2(a1.x * LOG2E, a1.y * LOG2E);
    A[3] = pack2(a1.z * LOG2E, a1.w * LOG2E);
    NC[0] = pack2(-c0.x, -c0.y);
    NC[1] = pack2(-c0.z, -c0.w);
    NC[2] = pack2(-c1.x, -c1.y);
    NC[3] = pack2(-c1.z, -c1.w);

    #pragma unroll
    for (int kp = 0; kp < 4; kp++) {
        const int k0 = (kg << 3) + 2 * kp;
        const int k1 = k0 + 1;
        const float scal0 = (float)(DIM - 1 - 2 * k0);
        const float scal1 = (float)(DIM - 1 - 2 * k1);
        const float M0 = fmaf(scal0, __ldg(&g_topv[(b << 8) + 255 - k0]),
                              -__ldg(&g_topB[(b << 8) + 255 - k0]));
        const float M1 = fmaf(scal1, __ldg(&g_topv[(b << 8) + 255 - k1]),
                              -__ldg(&g_topB[(b << 8) + 255 - k1]));

        const unsigned long long S20 = pack2(scal0, scal0);
        const unsigned long long S21 = pack2(scal1, scal1);
        const unsigned long long NM0 = pack2(-M0, -M0);
        const unsigned long long NM1 = pack2(-M1, -M1);

        float e0[8], e1[8];
        #pragma unroll
        for (int j = 0; j < 4; j++) {
            // l = a*scal - c - M, packed two-at-a-time
            unsigned long long L0 = fma2(A[j], S20, add2(NC[j], NM0));
            unsigned long long L1 = fma2(A[j], S21, add2(NC[j], NM1));
            float x0, y0, x1, y1;
            unpack2(L0, x0, y0);
            unpack2(L1, x1, y1);
            e0[2 * j]     = ex2f(x0);
            e0[2 * j + 1] = ex2f(y0);
            e1[2 * j]     = ex2f(x1);
            e1[2 * j + 1] = ex2f(y1);
        }

        float s0 = ((e0[0] + e0[1]) + (e0[2] + e0[3])) + ((e0[4] + e0[5]) + (e0[6] + e0[7]));
        float s1 = ((e1[0] + e1[1]) + (e1[2] + e1[3])) + ((e1[4] + e1[5]) + (e1[6] + e1[7]));
        #pragma unroll
        for (int o = 16; o; o >>= 1) {       // two independent chains overlap
            s0 += __shfl_xor_sync(0xffffffffu, s0, o);
            s1 += __shfl_xor_sync(0xffffffffu, s1, o);
        }
        const int p = (kp & 1) << 4;
        if (lane == 0) { redS[p + w] = s0; redS[p + 8 + w] = s1; }
        __syncthreads();                     // one barrier per 2 k's
        float S0 = redS[p + (lane & 7)];
        float S1 = redS[p + 8 + (lane & 7)];
        #pragma unroll
        for (int o = 4; o; o >>= 1) {
            S0 += __shfl_xor_sync(0xffffffffu, S0, o);
            S1 += __shfl_xor_sync(0xffffffffu, S1, o);
        }

        const float i0 = rcpf(S0);
        const float i1 = rcpf(S1);
        float4* o0p = (float4*)(out + ((size_t)((b << 8) + k0) << 11));
        float4* o1p = (float4*)(out + ((size_t)((b << 8) + k1) << 11));
        o0p[t]       = make_float4(e0[0] * i0, e0[1] * i0, e0[2] * i0, e0[3] * i0);
        o0p[t + 256] = make_float4(e0[4] * i0, e0[5] * i0, e0[6] * i0, e0[7] * i0);
        o1p[t]       = make_float4(e1[0] * i1, e1[1] * i1, e1[2] * i1, e1[3] * i1);
        o1p[t + 256] = make_float4(e1[4] * i1, e1[5] * i1, e1[6] * i1, e1[7] * i1);
    }
}

extern "C" void kernel_launch(void* const* d_in, const int* in_sizes, int n_in,
                              void* d_out, int out_size) {
    const float* scores = (const float*)d_in[0];
    float* out = (float*)d_out;

    chunk_rank_kernel<<<dim3(4, BATCH), 512>>>(scores);
    bsum_search_kernel<<<dim3(4, BATCH), 512>>>(scores);
    softmax_kernel<<<dim3(KTOP / 8, BATCH), 256>>>(scores, out);
}